// round 6
// baseline (speedup 1.0000x reference)
#include <cuda_runtime.h>

// Segment mean pooling: x [524288,128] f32, pointer [1025] i32 -> out [1024,128] f32.
//
// Kernel A: zero out, reset work counter, precompute chunk->first-segment map
//           (16384 parallel binary searches).
// Kernel B: persistent warps steal 32-row chunks via a global ticket counter
//           (next ticket prefetched to hide ATOMG latency). Each warp: lanes
//           own one float4 column, accumulate over the chunk's rows per
//           segment-intersection, flush inv-scaled partials via scalar
//           atomicAdd into out (sum of scaled partials == mean).

#define D_FEAT 128
#define D4 (D_FEAT / 4)       // 32 float4 per row
#define CW 32                 // rows per chunk
#define N_CHUNK_MAX 16384

__device__ int g_counter;
__device__ int g_chunk_seg[N_CHUNK_MAX];

__global__ __launch_bounds__(256) void setup_kernel(
    float4* __restrict__ out4, int n4,
    const int* __restrict__ ptr, int n_segs, int n_chunks)
{
    const int tid = blockIdx.x * blockDim.x + threadIdx.x;
    if (tid == 0) g_counter = 0;

    // zero output (n4 = 32768, 16384 threads -> 2 each)
    for (int i = tid; i < n4; i += gridDim.x * blockDim.x)
        out4[i] = make_float4(0.f, 0.f, 0.f, 0.f);

    // chunk -> largest seg with ptr[seg] <= chunk*CW
    if (tid < n_chunks) {
        const int base = tid * CW;
        int lo = 0, hi = n_segs - 1;
        while (lo < hi) {
            int mid = (lo + hi + 1) >> 1;
            if (__ldg(ptr + mid) <= base) lo = mid; else hi = mid - 1;
        }
        g_chunk_seg[tid] = lo;
    }
}

__global__ __launch_bounds__(256) void seg_accum_kernel(
    const float4* __restrict__ x4,
    const int* __restrict__ ptr,
    float* __restrict__ out,
    int n_rows, int n_chunks)
{
    const int lane = threadIdx.x & 31;
    const int c4   = lane;              // float4 column 0..31

    int c = 0;
    if (lane == 0) c = atomicAdd(&g_counter, 1);
    c = __shfl_sync(0xffffffffu, c, 0);

    while (c < n_chunks) {
        // prefetch next ticket; latency hides under this chunk's loads
        int c_next = 0;
        if (lane == 0) c_next = atomicAdd(&g_counter, 1);

        const int base = c * CW;
        const int cend = min(base + CW, n_rows);
        int seg = g_chunk_seg[c];

        for (;;) {
            const int seg_beg = __ldg(ptr + seg);
            const int seg_end = __ldg(ptr + seg + 1);
            const int s = max(seg_beg, base);
            const int e = min(seg_end, cend);

            if (e > s) {
                float4 acc = make_float4(0.f, 0.f, 0.f, 0.f);
                #pragma unroll 8
                for (int row = s; row < e; row++) {
                    const float4 v = x4[(size_t)row * D4 + c4];
                    acc.x += v.x; acc.y += v.y; acc.z += v.z; acc.w += v.w;
                }
                const int cnt = seg_end - seg_beg;
                const float inv = 1.0f / (float)cnt;   // cnt >= 1 since e > s
                float* o = out + (size_t)seg * D_FEAT + c4 * 4;
                atomicAdd(o + 0, acc.x * inv);
                atomicAdd(o + 1, acc.y * inv);
                atomicAdd(o + 2, acc.z * inv);
                atomicAdd(o + 3, acc.w * inv);
            }
            if (seg_end >= cend) break;
            seg++;
        }

        c = __shfl_sync(0xffffffffu, c_next, 0);
    }
}

extern "C" void kernel_launch(void* const* d_in, const int* in_sizes, int n_in,
                              void* d_out, int out_size)
{
    const float4* x4  = (const float4*)d_in[0];
    const int*    ptr = (const int*)d_in[1];
    float*        out = (float*)d_out;

    const int n_rows   = in_sizes[0] / D_FEAT;          // 524288
    const int n_segs   = in_sizes[1] - 1;               // 1024
    const int out_f4   = out_size / 4;                  // 32768
    const int n_chunks = (n_rows + CW - 1) / CW;        // 16384

    setup_kernel<<<64, 256>>>((float4*)out, out_f4, ptr, n_segs, n_chunks);
    seg_accum_kernel<<<592, 256>>>(x4, ptr, out, n_rows, n_chunks);
}

// round 7
// speedup vs baseline: 1.1187x; 1.1187x over previous
#include <cuda_runtime.h>

// Segment mean pooling: x [524288,128] f32, pointer [1025] i32 -> out [1024,128] f32.
//
// Kernel A (setup): zero out, reset ticket counter, precompute chunk->first-seg
//   map (4096 parallel binary searches).
// Kernel B (accum): 1184 persistent CTAs steal 128-row chunks via a CTA-level
//   ticket counter (leader prefetches the next ticket before the body, hiding
//   ATOMG latency). Chunk body = R4 engine: 8 warps x stride-8 rows x 32
//   float4 columns, smem-reduce 8->1 per segment intersection, warp 0 flushes
//   inv-scaled partials with scalar atomicAdd (sum of scaled partials == mean).

#define D_FEAT 128
#define D4 (D_FEAT / 4)       // 32 float4 per row
#define CHUNK 128             // rows per ticket
#define N_CHUNK_MAX 4096

__device__ int g_counter;
__device__ int g_chunk_seg[N_CHUNK_MAX];

__global__ __launch_bounds__(256) void setup_kernel(
    float4* __restrict__ out4, int n4,
    const int* __restrict__ ptr, int n_segs, int n_chunks)
{
    const int tid = blockIdx.x * blockDim.x + threadIdx.x;
    if (tid == 0) g_counter = 0;

    for (int i = tid; i < n4; i += gridDim.x * blockDim.x)
        out4[i] = make_float4(0.f, 0.f, 0.f, 0.f);

    if (tid < n_chunks) {
        const int base = tid * CHUNK;
        int lo = 0, hi = n_segs - 1;
        while (lo < hi) {
            int mid = (lo + hi + 1) >> 1;
            if (__ldg(ptr + mid) <= base) lo = mid; else hi = mid - 1;
        }
        g_chunk_seg[tid] = lo;   // largest seg with ptr[seg] <= base
    }
}

__global__ __launch_bounds__(256) void seg_accum_kernel(
    const float4* __restrict__ x4,
    const int* __restrict__ ptr,
    float* __restrict__ out,
    int n_rows, int n_chunks)
{
    const int c4 = threadIdx.x & 31;   // float4 column 0..31
    const int r  = threadIdx.x >> 5;   // row-lane warp 0..7

    __shared__ float4 sred[8][D4];     // 4 KB
    __shared__ int s_ticket;

    if (threadIdx.x == 0) s_ticket = atomicAdd(&g_counter, 1);
    __syncthreads();
    int cur = s_ticket;

    while (cur < n_chunks) {
        // Prefetch next ticket; consumed only after the body -> latency hidden.
        int nxt = 0;
        if (threadIdx.x == 0) nxt = atomicAdd(&g_counter, 1);

        const int base = cur * CHUNK;
        const int cend = min(base + CHUNK, n_rows);
        int seg = g_chunk_seg[cur];

        for (;;) {
            const int seg_beg = __ldg(ptr + seg);
            const int seg_end = __ldg(ptr + seg + 1);
            const int s = max(seg_beg, base);
            const int e = min(seg_end, cend);

            float4 acc = make_float4(0.f, 0.f, 0.f, 0.f);
            #pragma unroll 4
            for (int row = s + r; row < e; row += 8) {
                const float4 v = x4[(size_t)row * D4 + c4];
                acc.x += v.x; acc.y += v.y; acc.z += v.z; acc.w += v.w;
            }

            sred[r][c4] = acc;
            __syncthreads();
            if (r == 0 && e > s) {
                #pragma unroll
                for (int i = 1; i < 8; i++) {
                    const float4 v = sred[i][c4];
                    acc.x += v.x; acc.y += v.y; acc.z += v.z; acc.w += v.w;
                }
                const float inv = 1.0f / (float)(seg_end - seg_beg);
                float* o = out + (size_t)seg * D_FEAT + c4 * 4;
                atomicAdd(o + 0, acc.x * inv);
                atomicAdd(o + 1, acc.y * inv);
                atomicAdd(o + 2, acc.z * inv);
                atomicAdd(o + 3, acc.w * inv);
            }
            if (seg_end >= cend) break;
            seg++;
            __syncthreads();   // sred reuse safety
        }

        __syncthreads();       // all done with sred + s_ticket
        if (threadIdx.x == 0) s_ticket = nxt;
        __syncthreads();
        cur = s_ticket;
    }
}

extern "C" void kernel_launch(void* const* d_in, const int* in_sizes, int n_in,
                              void* d_out, int out_size)
{
    const float4* x4  = (const float4*)d_in[0];
    const int*    ptr = (const int*)d_in[1];
    float*        out = (float*)d_out;

    const int n_rows   = in_sizes[0] / D_FEAT;        // 524288
    const int n_segs   = in_sizes[1] - 1;             // 1024
    const int out_f4   = out_size / 4;                // 32768
    const int n_chunks = (n_rows + CHUNK - 1) / CHUNK; // 4096

    setup_kernel<<<32, 256>>>((float4*)out, out_f4, ptr, n_segs, n_chunks);
    seg_accum_kernel<<<1184, 256>>>(x4, ptr, out, n_rows, n_chunks);
}

// round 8
// speedup vs baseline: 1.1836x; 1.0580x over previous
#include <cuda_runtime.h>

// Segment mean pooling: x [524288,128] f32, pointer [1025] i32 -> out [1024,128] f32.
//
// Kernel 1: zero out (harness poisons it).
// Kernel 2: static grid 1024 x 512-row chunks (R4 chassis, lowest overhead).
//   Inner loop processes 2 rows per step (stride 16 per warp) into TWO
//   accumulators with #pragma unroll 4 -> 8 independent LDG.128 in flight per
//   thread (2x R4) and half the dependent-FADD chain, raising the per-warp
//   MLP equilibrium that pinned R4/R7 at 5.75 TB/s.
//   Flush: smem-reduce 8 warps -> 1, warp 0 scalar-atomicAdds inv-scaled
//   partials into out (sum of scaled partials == mean).

#define D_FEAT 128
#define D4 (D_FEAT / 4)     // 32 float4 per row
#define CHUNK 512           // rows per CTA

__global__ __launch_bounds__(128) void zero_out_kernel(float4* __restrict__ out4, int n4)
{
    int i = blockIdx.x * blockDim.x + threadIdx.x;
    if (i < n4) out4[i] = make_float4(0.f, 0.f, 0.f, 0.f);
}

__global__ __launch_bounds__(256) void seg_accum_kernel(
    const float4* __restrict__ x4,
    const int* __restrict__ ptr,
    float* __restrict__ out,
    int n_rows, int n_segs)
{
    const int base = blockIdx.x * CHUNK;
    if (base >= n_rows) return;
    const int cend = min(base + CHUNK, n_rows);
    const int c4 = threadIdx.x & 31;   // float4 column 0..31
    const int r  = threadIdx.x >> 5;   // row-lane warp 0..7

    __shared__ float4 sred[8][D4];     // 4 KB

    // First segment overlapping the chunk (CTA-uniform -> broadcast L1 hits).
    int lo = 0, hi = n_segs - 1;
    while (lo < hi) {
        int mid = (lo + hi + 1) >> 1;
        if (__ldg(ptr + mid) <= base) lo = mid; else hi = mid - 1;
    }
    int seg = lo;

    for (;;) {
        const int seg_beg = __ldg(ptr + seg);
        const int seg_end = __ldg(ptr + seg + 1);
        const int s = max(seg_beg, base);
        const int e = min(seg_end, cend);

        float4 a0 = make_float4(0.f, 0.f, 0.f, 0.f);
        float4 a1 = make_float4(0.f, 0.f, 0.f, 0.f);

        int row = s + r;
        // Main loop: 2 rows/step, 2 independent accumulators; unroll 4 ->
        // 8 independent 16B loads batched per thread per iteration group.
        #pragma unroll 4
        for (; row + 8 < e; row += 16) {
            const float4 v0 = x4[(size_t)row * D4 + c4];
            const float4 v1 = x4[(size_t)(row + 8) * D4 + c4];
            a0.x += v0.x; a0.y += v0.y; a0.z += v0.z; a0.w += v0.w;
            a1.x += v1.x; a1.y += v1.y; a1.z += v1.z; a1.w += v1.w;
        }
        if (row < e) {
            const float4 v = x4[(size_t)row * D4 + c4];
            a0.x += v.x; a0.y += v.y; a0.z += v.z; a0.w += v.w;
        }
        a0.x += a1.x; a0.y += a1.y; a0.z += a1.z; a0.w += a1.w;

        // 8 warp-partials -> 1; warp 0 flushes the inv-scaled partial.
        sred[r][c4] = a0;
        __syncthreads();
        if (r == 0 && e > s) {
            #pragma unroll
            for (int i = 1; i < 8; i++) {
                const float4 v = sred[i][c4];
                a0.x += v.x; a0.y += v.y; a0.z += v.z; a0.w += v.w;
            }
            const float inv = 1.0f / (float)(seg_end - seg_beg);
            float* o = out + (size_t)seg * D_FEAT + c4 * 4;
            atomicAdd(o + 0, a0.x * inv);
            atomicAdd(o + 1, a0.y * inv);
            atomicAdd(o + 2, a0.z * inv);
            atomicAdd(o + 3, a0.w * inv);
        }
        if (seg_end >= cend) break;
        seg++;
        __syncthreads();   // sred reuse safety
    }
}

extern "C" void kernel_launch(void* const* d_in, const int* in_sizes, int n_in,
                              void* d_out, int out_size)
{
    const float4* x4  = (const float4*)d_in[0];
    const int*    ptr = (const int*)d_in[1];
    float*        out = (float*)d_out;

    const int n_rows = in_sizes[0] / D_FEAT;   // 524288
    const int n_segs = in_sizes[1] - 1;        // 1024
    const int out_f4 = out_size / 4;           // 32768

    zero_out_kernel<<<(out_f4 + 127) / 128, 128>>>((float4*)out, out_f4);

    const int n_chunks = (n_rows + CHUNK - 1) / CHUNK;   // 1024
    seg_accum_kernel<<<n_chunks, 256>>>(x4, ptr, out, n_rows, n_segs);
}